// round 2
// baseline (speedup 1.0000x reference)
#include <cuda_runtime.h>
#include <math.h>

// Problem constants (fixed shapes from reference)
#define T_TOK 2048          // B*S tokens
#define H_DIM 2048          // hidden
#define I_DIM 1408          // intermediate
#define N1    (2*I_DIM)     // 2816 = gate_up out dim
#define E_NUM 8
#define NPAIR (2*T_TOK)     // 4096 token-expert pairs (top-2, always distinct)

// ---------------- device scratch (static: no allocation allowed) -------------
__device__ int   g_cnt[E_NUM];
__device__ int   g_off[E_NUM];
__device__ int   g_cur[E_NUM];
__device__ int   g_tok_e[T_TOK][2];
__device__ float g_tok_w[T_TOK][2];
__device__ int   g_row_tok[NPAIR];
__device__ float g_row_w[NPAIR];
__device__ float g_gu[NPAIR][N1];     // 46.1 MB gate_up
__device__ float g_act[NPAIR][I_DIM]; // 23.1 MB silu(g)*u

// ---------------- init ----------------
__global__ void init_kernel() {
    int i = threadIdx.x;
    if (i < E_NUM) { g_cnt[i] = 0; g_cur[i] = 0; }
}

// ---------------- gating: logits -> top2 -> renorm weights ----------------
// one block per token; 8 warps, warp e computes dot(x[t], gate_w[e])
__global__ void gate_kernel(const float* __restrict__ x, const float* __restrict__ gw) {
    __shared__ float sx[H_DIM];
    __shared__ float logits[E_NUM];
    int t = blockIdx.x;
    const float* xr = x + (size_t)t * H_DIM;
    for (int i = threadIdx.x; i < H_DIM; i += blockDim.x) sx[i] = xr[i];
    __syncthreads();
    int w = threadIdx.x >> 5, lane = threadIdx.x & 31;
    const float* gr = gw + (size_t)w * H_DIM;
    float s = 0.f;
    for (int i = lane; i < H_DIM; i += 32) s += sx[i] * gr[i];
    #pragma unroll
    for (int o = 16; o; o >>= 1) s += __shfl_xor_sync(0xffffffffu, s, o);
    if (lane == 0) logits[w] = s;
    __syncthreads();
    if (threadIdx.x == 0) {
        int i0 = 0;
        #pragma unroll
        for (int e = 1; e < E_NUM; e++) if (logits[e] > logits[i0]) i0 = e;
        int i1 = (i0 == 0) ? 1 : 0;
        #pragma unroll
        for (int e = 0; e < E_NUM; e++) {
            if (e == i0 || e == i1) continue;
            if (logits[e] > logits[i1]) i1 = e;
        }
        // renormalized top-2 softmax weights
        float ex = expf(logits[i1] - logits[i0]);
        float w0 = 1.f / (1.f + ex);
        float w1 = ex / (1.f + ex);
        g_tok_e[t][0] = i0; g_tok_e[t][1] = i1;
        g_tok_w[t][0] = w0; g_tok_w[t][1] = w1;
        atomicAdd(&g_cnt[i0], 1); atomicAdd(&g_cnt[i1], 1);
    }
}

__global__ void offs_kernel() {
    if (threadIdx.x == 0) {
        int o = 0;
        #pragma unroll
        for (int e = 0; e < E_NUM; e++) { g_off[e] = o; o += g_cnt[e]; }
    }
}

// compact (token, k) pairs into per-expert contiguous row ranges
__global__ void scatter_kernel() {
    int t = blockIdx.x * blockDim.x + threadIdx.x;
    if (t >= T_TOK) return;
    #pragma unroll
    for (int k = 0; k < 2; k++) {
        int e = g_tok_e[t][k];
        int p = atomicAdd(&g_cur[e], 1);
        int r = g_off[e] + p;
        g_row_tok[r] = t;
        g_row_w[r]   = g_tok_w[t][k];
    }
}

// ---------------- GEMM1: gate_up[r, n] = sum_k x[tok(r), k] * w1[e, n, k] ----
// tiles: BM=128, BN=128, BK=8, 256 threads, 8x8 microtile, double-buffered smem
__global__ __launch_bounds__(256, 2)
void gemm1_kernel(const float* __restrict__ x, const float* __restrict__ w1) {
    int e = blockIdx.z;
    int cnt = g_cnt[e];
    int base = g_off[e];
    int m0 = blockIdx.y * 128;
    if (m0 >= cnt) return;
    int n0 = blockIdx.x * 128;
    const float* B = w1 + (size_t)e * N1 * H_DIM;

    __shared__ float As[2][8][128];
    __shared__ float Bs[2][8][128];

    int tid  = threadIdx.x;
    int lrow = tid >> 1;           // 0..127 (tile row for A / tile col-row for B)
    int lcol = (tid & 1) * 4;      // 0 or 4 (k offset)

    bool avalid = (m0 + lrow) < cnt;
    const float* aptr = avalid
        ? x + (size_t)g_row_tok[base + m0 + lrow] * H_DIM + lcol
        : x;  // dummy, never dereferenced when !avalid
    const float* bptr = B + (size_t)(n0 + lrow) * H_DIM + lcol;

    int tx = tid & 15, ty = tid >> 4;
    float acc[8][8];
    #pragma unroll
    for (int i = 0; i < 8; i++)
        #pragma unroll
        for (int j = 0; j < 8; j++) acc[i][j] = 0.f;

    const int nk = H_DIM / 8;  // 256
    float4 ar, br;
    ar = avalid ? *(const float4*)aptr : make_float4(0.f, 0.f, 0.f, 0.f);
    br = *(const float4*)bptr;
    As[0][lcol+0][lrow] = ar.x; As[0][lcol+1][lrow] = ar.y;
    As[0][lcol+2][lrow] = ar.z; As[0][lcol+3][lrow] = ar.w;
    Bs[0][lcol+0][lrow] = br.x; Bs[0][lcol+1][lrow] = br.y;
    Bs[0][lcol+2][lrow] = br.z; Bs[0][lcol+3][lrow] = br.w;
    __syncthreads();

    for (int kt = 0; kt < nk; kt++) {
        int buf = kt & 1;
        if (kt + 1 < nk) {
            ar = avalid ? *(const float4*)(aptr + (kt + 1) * 8)
                        : make_float4(0.f, 0.f, 0.f, 0.f);
            br = *(const float4*)(bptr + (kt + 1) * 8);
        }
        #pragma unroll
        for (int kk = 0; kk < 8; kk++) {
            float a[8], b[8];
            *(float4*)&a[0] = *(const float4*)&As[buf][kk][ty * 8];
            *(float4*)&a[4] = *(const float4*)&As[buf][kk][ty * 8 + 4];
            *(float4*)&b[0] = *(const float4*)&Bs[buf][kk][tx * 8];
            *(float4*)&b[4] = *(const float4*)&Bs[buf][kk][tx * 8 + 4];
            #pragma unroll
            for (int i = 0; i < 8; i++)
                #pragma unroll
                for (int j = 0; j < 8; j++)
                    acc[i][j] = fmaf(a[i], b[j], acc[i][j]);
        }
        if (kt + 1 < nk) {
            int nb = buf ^ 1;
            As[nb][lcol+0][lrow] = ar.x; As[nb][lcol+1][lrow] = ar.y;
            As[nb][lcol+2][lrow] = ar.z; As[nb][lcol+3][lrow] = ar.w;
            Bs[nb][lcol+0][lrow] = br.x; Bs[nb][lcol+1][lrow] = br.y;
            Bs[nb][lcol+2][lrow] = br.z; Bs[nb][lcol+3][lrow] = br.w;
            __syncthreads();
        }
    }

    #pragma unroll
    for (int i = 0; i < 8; i++) {
        int m = m0 + ty * 8 + i;
        if (m < cnt) {
            float* o = &g_gu[base + m][n0 + tx * 8];
            *(float4*)o       = make_float4(acc[i][0], acc[i][1], acc[i][2], acc[i][3]);
            *(float4*)(o + 4) = make_float4(acc[i][4], acc[i][5], acc[i][6], acc[i][7]);
        }
    }
}

// ---------------- activation: act = silu(g) * u ----------------
__global__ void act_kernel() {
    int idx = blockIdx.x * blockDim.x + threadIdx.x;
    const int total = NPAIR * (I_DIM / 4);
    if (idx >= total) return;
    int r  = idx / (I_DIM / 4);
    int c4 = (idx % (I_DIM / 4)) * 4;
    float4 g = *(const float4*)&g_gu[r][c4];
    float4 u = *(const float4*)&g_gu[r][I_DIM + c4];
    float4 o;
    o.x = g.x / (1.f + expf(-g.x)) * u.x;
    o.y = g.y / (1.f + expf(-g.y)) * u.y;
    o.z = g.z / (1.f + expf(-g.z)) * u.z;
    o.w = g.w / (1.f + expf(-g.w)) * u.w;
    *(float4*)&g_act[r][c4] = o;
}

// ---------------- GEMM2: out[tok, h] += rw * sum_i act[r, i] * w2[e, h, i] ---
__global__ __launch_bounds__(256, 2)
void gemm2_kernel(const float* __restrict__ w2, float* __restrict__ out) {
    int e = blockIdx.z;
    int cnt = g_cnt[e];
    int base = g_off[e];
    int m0 = blockIdx.y * 128;
    if (m0 >= cnt) return;
    int n0 = blockIdx.x * 128;
    const float* B = w2 + (size_t)e * H_DIM * I_DIM;

    __shared__ float As[2][8][128];
    __shared__ float Bs[2][8][128];

    int tid  = threadIdx.x;
    int lrow = tid >> 1;
    int lcol = (tid & 1) * 4;

    bool avalid = (m0 + lrow) < cnt;
    const float* aptr = avalid ? &g_act[base + m0 + lrow][lcol] : &g_act[0][0];
    const float* bptr = B + (size_t)(n0 + lrow) * I_DIM + lcol;

    int tx = tid & 15, ty = tid >> 4;
    float acc[8][8];
    #pragma unroll
    for (int i = 0; i < 8; i++)
        #pragma unroll
        for (int j = 0; j < 8; j++) acc[i][j] = 0.f;

    const int nk = I_DIM / 8;  // 176
    float4 ar, br;
    ar = avalid ? *(const float4*)aptr : make_float4(0.f, 0.f, 0.f, 0.f);
    br = *(const float4*)bptr;
    As[0][lcol+0][lrow] = ar.x; As[0][lcol+1][lrow] = ar.y;
    As[0][lcol+2][lrow] = ar.z; As[0][lcol+3][lrow] = ar.w;
    Bs[0][lcol+0][lrow] = br.x; Bs[0][lcol+1][lrow] = br.y;
    Bs[0][lcol+2][lrow] = br.z; Bs[0][lcol+3][lrow] = br.w;
    __syncthreads();

    for (int kt = 0; kt < nk; kt++) {
        int buf = kt & 1;
        if (kt + 1 < nk) {
            ar = avalid ? *(const float4*)(aptr + (kt + 1) * 8)
                        : make_float4(0.f, 0.f, 0.f, 0.f);
            br = *(const float4*)(bptr + (kt + 1) * 8);
        }
        #pragma unroll
        for (int kk = 0; kk < 8; kk++) {
            float a[8], b[8];
            *(float4*)&a[0] = *(const float4*)&As[buf][kk][ty * 8];
            *(float4*)&a[4] = *(const float4*)&As[buf][kk][ty * 8 + 4];
            *(float4*)&b[0] = *(const float4*)&Bs[buf][kk][tx * 8];
            *(float4*)&b[4] = *(const float4*)&Bs[buf][kk][tx * 8 + 4];
            #pragma unroll
            for (int i = 0; i < 8; i++)
                #pragma unroll
                for (int j = 0; j < 8; j++)
                    acc[i][j] = fmaf(a[i], b[j], acc[i][j]);
        }
        if (kt + 1 < nk) {
            int nb = buf ^ 1;
            As[nb][lcol+0][lrow] = ar.x; As[nb][lcol+1][lrow] = ar.y;
            As[nb][lcol+2][lrow] = ar.z; As[nb][lcol+3][lrow] = ar.w;
            Bs[nb][lcol+0][lrow] = br.x; Bs[nb][lcol+1][lrow] = br.y;
            Bs[nb][lcol+2][lrow] = br.z; Bs[nb][lcol+3][lrow] = br.w;
            __syncthreads();
        }
    }

    // epilogue: weighted atomic accumulate into out[token, h]
    #pragma unroll
    for (int i = 0; i < 8; i++) {
        int m = m0 + ty * 8 + i;
        if (m < cnt) {
            int r   = base + m;
            int tok = g_row_tok[r];
            float rw = g_row_w[r];
            float* o = out + (size_t)tok * H_DIM + n0 + tx * 8;
            #pragma unroll
            for (int j = 0; j < 8; j++)
                atomicAdd(o + j, rw * acc[i][j]);
        }
    }
}

// ---------------- launch ----------------
extern "C" void kernel_launch(void* const* d_in, const int* in_sizes, int n_in,
                              void* d_out, int out_size) {
    const float* x  = (const float*)d_in[0];  // [T, H]
    const float* gw = (const float*)d_in[1];  // [E, H]
    const float* w1 = (const float*)d_in[2];  // [E, 2I, H]
    const float* w2 = (const float*)d_in[3];  // [E, H, I]
    float* out = (float*)d_out;               // [T, H]

    cudaMemsetAsync(out, 0, (size_t)out_size * sizeof(float), 0);
    init_kernel<<<1, 32>>>();
    gate_kernel<<<T_TOK, 256>>>(x, gw);
    offs_kernel<<<1, 32>>>();
    scatter_kernel<<<(T_TOK + 255) / 256, 256>>>();

    dim3 grid1(N1 / 128, T_TOK / 128, E_NUM);      // 22 x 16 x 8
    gemm1_kernel<<<grid1, 256>>>(x, w1);

    int actth = NPAIR * (I_DIM / 4);
    act_kernel<<<(actth + 255) / 256, 256>>>();

    dim3 grid2(H_DIM / 128, T_TOK / 128, E_NUM);   // 16 x 16 x 8
    gemm2_kernel<<<grid2, 256>>>(w2, out);
}

// round 8
// speedup vs baseline: 1.7475x; 1.7475x over previous
#include <cuda_runtime.h>
#include <cuda_bf16.h>
#include <math.h>
#include <stdint.h>

// ---------------- problem constants ----------------
#define T_TOK 2048
#define H_DIM 2048
#define I_DIM 1408
#define N1    (2*I_DIM)     // 2816
#define E_NUM 8
#define NPAIR (2*T_TOK)     // 4096

// ---------------- device scratch ----------------
__device__ int   g_cnt[E_NUM];
__device__ int   g_off[E_NUM];
__device__ int   g_cur[E_NUM];
__device__ int   g_tok_e[T_TOK][2];
__device__ float g_tok_w[T_TOK][2];
__device__ int   g_tok_row[T_TOK][2];
__device__ int   g_row_tok[NPAIR];
__device__ float g_gu[NPAIR][N1];      // gate_up
__device__ float g_act[NPAIR][I_DIM];  // silu(g)*u
__device__ float g_eo[NPAIR][H_DIM];   // expert_out (unweighted)

// ---------------- helpers ----------------
__device__ __forceinline__ uint32_t smem_u32(const void* p) {
    uint32_t a;
    asm("{ .reg .u64 t; cvta.to.shared.u64 t, %1; cvt.u32.u64 %0, t; }" : "=r"(a) : "l"(p));
    return a;
}
#define CP16(dst, src, nbytes) \
    asm volatile("cp.async.ca.shared.global [%0], [%1], 16, %2;" \
                 :: "r"(dst), "l"(src), "r"(nbytes))
#define CP_COMMIT() asm volatile("cp.async.commit_group;" ::: "memory")
#define CP_WAIT(n)  asm volatile("cp.async.wait_group %0;" :: "n"(n) : "memory")

// bf16 m16n8k16 mma: a = 4 x b32 (bf16x2), b = 2 x b32, c = 4 x f32
__device__ __forceinline__ void mma_bf16(float& c0, float& c1, float& c2, float& c3,
                                         uint32_t a0, uint32_t a1, uint32_t a2, uint32_t a3,
                                         uint32_t b0, uint32_t b1) {
    asm volatile(
        "mma.sync.aligned.m16n8k16.row.col.f32.bf16.bf16.f32 "
        "{%0,%1,%2,%3}, {%4,%5,%6,%7}, {%8,%9}, {%0,%1,%2,%3};"
        : "+f"(c0), "+f"(c1), "+f"(c2), "+f"(c3)
        : "r"(a0), "r"(a1), "r"(a2), "r"(a3), "r"(b0), "r"(b1));
}

// split (x,y) fp32 pair into packed bf16x2 hi (low half = x) and bf16x2 lo residual
__device__ __forceinline__ void split2(float x, float y, uint32_t& hi, uint32_t& lo) {
    uint32_t h;
    asm("cvt.rn.bf16x2.f32 %0, %1, %2;" : "=r"(h) : "f"(y), "f"(x));  // high = y, low = x
    float hx = __uint_as_float(h << 16);
    float hy = __uint_as_float(h & 0xFFFF0000u);
    float lx = x - hx, ly = y - hy;
    asm("cvt.rn.bf16x2.f32 %0, %1, %2;" : "=r"(lo) : "f"(ly), "f"(lx));
    hi = h;
}

// smem geometry: 128 rows x 32 floats, stride 36 floats (2-phase-min float2 access)
#define SROW 36
#define BUF_FLOATS (128 * SROW)              // 4608
#define SMEM_FLOATS (4 * BUF_FLOATS)         // A[2] + B[2]
#define SMEM_BYTES (SMEM_FLOATS * 4)         // 73728

// ---------------- init / gating / scatter ----------------
__global__ void init_kernel() {
    int i = threadIdx.x;
    if (i < E_NUM) { g_cnt[i] = 0; g_cur[i] = 0; }
}

__global__ void gate_kernel(const float* __restrict__ x, const float* __restrict__ gw) {
    __shared__ float sx[H_DIM];
    __shared__ float logits[E_NUM];
    int t = blockIdx.x;
    const float* xr = x + (size_t)t * H_DIM;
    for (int i = threadIdx.x; i < H_DIM; i += blockDim.x) sx[i] = xr[i];
    __syncthreads();
    int w = threadIdx.x >> 5, lane = threadIdx.x & 31;
    const float* gr = gw + (size_t)w * H_DIM;
    float s = 0.f;
    for (int i = lane; i < H_DIM; i += 32) s += sx[i] * gr[i];
    #pragma unroll
    for (int o = 16; o; o >>= 1) s += __shfl_xor_sync(0xffffffffu, s, o);
    if (lane == 0) logits[w] = s;
    __syncthreads();
    if (threadIdx.x == 0) {
        int i0 = 0;
        #pragma unroll
        for (int e = 1; e < E_NUM; e++) if (logits[e] > logits[i0]) i0 = e;
        int i1 = (i0 == 0) ? 1 : 0;
        #pragma unroll
        for (int e = 0; e < E_NUM; e++) {
            if (e == i0 || e == i1) continue;
            if (logits[e] > logits[i1]) i1 = e;
        }
        float ex = expf(logits[i1] - logits[i0]);
        float w0 = 1.f / (1.f + ex);
        float w1 = ex / (1.f + ex);
        g_tok_e[t][0] = i0; g_tok_e[t][1] = i1;
        g_tok_w[t][0] = w0; g_tok_w[t][1] = w1;
        atomicAdd(&g_cnt[i0], 1); atomicAdd(&g_cnt[i1], 1);
    }
}

__global__ void offs_kernel() {
    if (threadIdx.x == 0) {
        int o = 0;
        #pragma unroll
        for (int e = 0; e < E_NUM; e++) { g_off[e] = o; o += g_cnt[e]; }
    }
}

__global__ void scatter_kernel() {
    int t = blockIdx.x * blockDim.x + threadIdx.x;
    if (t >= T_TOK) return;
    #pragma unroll
    for (int k = 0; k < 2; k++) {
        int e = g_tok_e[t][k];
        int p = atomicAdd(&g_cur[e], 1);
        int r = g_off[e] + p;
        g_row_tok[r] = t;
        g_tok_row[t][k] = r;
    }
}

// ---------------- bf16x3 mma.sync grouped GEMM ----------------
// C[row, n] = sum_k A[row, k] * W_e[n, k]   (W row-major [NROWS, KSTRIDE])
// GATHER: A row = x[g_row_tok[row]]; else A row = g_act[row].
// 128x128x32 tiles; 8 warps as 2(m) x 4(n), warp tile 64x32, mma m16n8k16 bf16,
// fp32 operands split hi/lo, 3-term products (hh + hl + lh).
template<int NK, int KSTRIDE, int NROWS, int OUTSTRIDE, bool GATHER>
__global__ __launch_bounds__(256, 1)
void moe_gemm(const float* __restrict__ Axt, const float* __restrict__ W) {
    extern __shared__ float smf[];
    const int e    = blockIdx.z;
    const int cnt  = g_cnt[e];
    const int base = g_off[e];
    const int m0   = blockIdx.y * 128;
    if (m0 >= cnt) return;
    const int n0 = blockIdx.x * 128;

    float* As = smf;                      // 2 x BUF_FLOATS
    float* Bs = smf + 2 * BUF_FLOATS;     // 2 x BUF_FLOATS

    const int tid  = threadIdx.x;
    const int lane = tid & 31;
    const int wid  = tid >> 5;
    const int wm   = wid >> 2;            // 0..1 -> m offset wm*64
    const int wn   = wid & 3;             // 0..3 -> n offset wn*32

    // cp.async staging: thread covers one row, 4 consecutive 16B chunks
    const int srow  = tid >> 1;           // 0..127
    const int ubase = (tid & 1) * 4;      // chunk 0..3 or 4..7
    const bool a_ok = (m0 + srow) < cnt;
    const float* aRow;
    if (GATHER)
        aRow = a_ok ? Axt + (size_t)g_row_tok[base + m0 + srow] * KSTRIDE : Axt;
    else
        aRow = a_ok ? &g_act[0][0] + (size_t)(base + m0 + srow) * KSTRIDE : &g_act[0][0];
    const float* bRow = W + (size_t)e * NROWS * KSTRIDE + (size_t)(n0 + srow) * KSTRIDE;

    const uint32_t sA = smem_u32(As);
    const uint32_t sB = smem_u32(Bs);
    const int a_n = a_ok ? 16 : 0;

    auto stage = [&](int kt, int b) {
        uint32_t ab = sA + (uint32_t)(b * BUF_FLOATS * 4);
        uint32_t bb = sB + (uint32_t)(b * BUF_FLOATS * 4);
        #pragma unroll
        for (int jj = 0; jj < 4; jj++) {
            int u = ubase + jj;
            uint32_t doff = (uint32_t)((srow * SROW + u * 4) * 4);
            CP16(ab + doff, aRow + kt * 32 + u * 4, a_n);
            CP16(bb + doff, bRow + kt * 32 + u * 4, 16);
        }
        CP_COMMIT();
    };

    stage(0, 0);
    stage(1, 1);

    float acc[4][4][4];
    #pragma unroll
    for (int i = 0; i < 4; i++)
        #pragma unroll
        for (int j = 0; j < 4; j++)
            #pragma unroll
            for (int q = 0; q < 4; q++) acc[i][j][q] = 0.f;

    const int qrow = lane >> 2;   // 0..7
    const int qk   = lane & 3;    // 0..3

    for (int kt = 0; kt < NK; kt++) {
        if (kt == NK - 1) CP_WAIT(0); else CP_WAIT(1);
        __syncthreads();
        const float* Ab = As + (kt & 1) * BUF_FLOATS;
        const float* Bb = Bs + (kt & 1) * BUF_FLOATS;
        #pragma unroll
        for (int ks = 0; ks < 2; ks++) {
            const int k0 = ks * 16 + qk * 2;
            // A fragments: hi/lo packed bf16x2, 4 regs each per mf
            uint32_t ah[4][4], al[4][4];
            #pragma unroll
            for (int mf = 0; mf < 4; mf++) {
                int r = wm * 64 + mf * 16 + qrow;
                float2 p0 = *(const float2*)&Ab[r * SROW + k0];
                float2 p1 = *(const float2*)&Ab[(r + 8) * SROW + k0];
                float2 p2 = *(const float2*)&Ab[r * SROW + k0 + 8];
                float2 p3 = *(const float2*)&Ab[(r + 8) * SROW + k0 + 8];
                split2(p0.x, p0.y, ah[mf][0], al[mf][0]);
                split2(p1.x, p1.y, ah[mf][1], al[mf][1]);
                split2(p2.x, p2.y, ah[mf][2], al[mf][2]);
                split2(p3.x, p3.y, ah[mf][3], al[mf][3]);
            }
            uint32_t bh[4][2], bl[4][2];
            #pragma unroll
            for (int nf = 0; nf < 4; nf++) {
                int nn = wn * 32 + nf * 8 + qrow;
                float2 p0 = *(const float2*)&Bb[nn * SROW + k0];
                float2 p1 = *(const float2*)&Bb[nn * SROW + k0 + 8];
                split2(p0.x, p0.y, bh[nf][0], bl[nf][0]);
                split2(p1.x, p1.y, bh[nf][1], bl[nf][1]);
            }
            #pragma unroll
            for (int mf = 0; mf < 4; mf++)
                #pragma unroll
                for (int nf = 0; nf < 4; nf++) {
                    mma_bf16(acc[mf][nf][0], acc[mf][nf][1], acc[mf][nf][2], acc[mf][nf][3],
                             ah[mf][0], ah[mf][1], ah[mf][2], ah[mf][3],
                             bh[nf][0], bh[nf][1]);
                    mma_bf16(acc[mf][nf][0], acc[mf][nf][1], acc[mf][nf][2], acc[mf][nf][3],
                             ah[mf][0], ah[mf][1], ah[mf][2], ah[mf][3],
                             bl[nf][0], bl[nf][1]);
                    mma_bf16(acc[mf][nf][0], acc[mf][nf][1], acc[mf][nf][2], acc[mf][nf][3],
                             al[mf][0], al[mf][1], al[mf][2], al[mf][3],
                             bh[nf][0], bh[nf][1]);
                }
        }
        __syncthreads();
        if (kt + 2 < NK) stage(kt + 2, kt & 1);
    }

    // epilogue (c frag: rows qrow/+8, cols qk*2,+1 — same as m16n8k8)
    float* Out = GATHER ? &g_gu[0][0] : &g_eo[0][0];
    #pragma unroll
    for (int mf = 0; mf < 4; mf++) {
        int ml = wm * 64 + mf * 16 + qrow;
        int m1 = m0 + ml;
        int m2 = m1 + 8;
        #pragma unroll
        for (int nf = 0; nf < 4; nf++) {
            int col = n0 + wn * 32 + nf * 8 + qk * 2;
            if (m1 < cnt) {
                float2 v = make_float2(acc[mf][nf][0], acc[mf][nf][1]);
                *(float2*)(Out + (size_t)(base + m1) * OUTSTRIDE + col) = v;
            }
            if (m2 < cnt) {
                float2 v = make_float2(acc[mf][nf][2], acc[mf][nf][3]);
                *(float2*)(Out + (size_t)(base + m2) * OUTSTRIDE + col) = v;
            }
        }
    }
}

// ---------------- activation ----------------
__global__ void act_kernel() {
    int idx = blockIdx.x * blockDim.x + threadIdx.x;
    const int total = NPAIR * (I_DIM / 4);
    if (idx >= total) return;
    int r  = idx / (I_DIM / 4);
    int c4 = (idx % (I_DIM / 4)) * 4;
    float4 g = *(const float4*)&g_gu[r][c4];
    float4 u = *(const float4*)&g_gu[r][I_DIM + c4];
    float4 o;
    o.x = g.x / (1.f + expf(-g.x)) * u.x;
    o.y = g.y / (1.f + expf(-g.y)) * u.y;
    o.z = g.z / (1.f + expf(-g.z)) * u.z;
    o.w = g.w / (1.f + expf(-g.w)) * u.w;
    *(float4*)&g_act[r][c4] = o;
}

// ---------------- combine: out[t] = w0*eo[r0] + w1*eo[r1] ----------------
__global__ void combine_kernel(float* __restrict__ out) {
    int idx = blockIdx.x * blockDim.x + threadIdx.x;
    const int per_tok = H_DIM / 4;
    if (idx >= T_TOK * per_tok) return;
    int t  = idx / per_tok;
    int c4 = (idx % per_tok) * 4;
    int r0 = g_tok_row[t][0], r1 = g_tok_row[t][1];
    float w0 = g_tok_w[t][0], w1 = g_tok_w[t][1];
    float4 a = *(const float4*)&g_eo[r0][c4];
    float4 b = *(const float4*)&g_eo[r1][c4];
    float4 o;
    o.x = w0 * a.x + w1 * b.x;
    o.y = w0 * a.y + w1 * b.y;
    o.z = w0 * a.z + w1 * b.z;
    o.w = w0 * a.w + w1 * b.w;
    *(float4*)(out + (size_t)t * H_DIM + c4) = o;
}

// ---------------- launch ----------------
extern "C" void kernel_launch(void* const* d_in, const int* in_sizes, int n_in,
                              void* d_out, int out_size) {
    const float* x  = (const float*)d_in[0];
    const float* gw = (const float*)d_in[1];
    const float* w1 = (const float*)d_in[2];
    const float* w2 = (const float*)d_in[3];
    float* out = (float*)d_out;

    cudaFuncSetAttribute(moe_gemm<H_DIM/32, H_DIM, N1, N1, true>,
                         cudaFuncAttributeMaxDynamicSharedMemorySize, SMEM_BYTES);
    cudaFuncSetAttribute(moe_gemm<I_DIM/32, I_DIM, H_DIM, H_DIM, false>,
                         cudaFuncAttributeMaxDynamicSharedMemorySize, SMEM_BYTES);

    init_kernel<<<1, 32>>>();
    gate_kernel<<<T_TOK, 256>>>(x, gw);
    offs_kernel<<<1, 32>>>();
    scatter_kernel<<<(T_TOK + 255) / 256, 256>>>();

    dim3 grid1(N1 / 128, T_TOK / 128, E_NUM);    // 22 x 16 x 8
    moe_gemm<H_DIM/32, H_DIM, N1, N1, true><<<grid1, 256, SMEM_BYTES>>>(x, w1);

    int actth = NPAIR * (I_DIM / 4);
    act_kernel<<<(actth + 255) / 256, 256>>>();

    dim3 grid2(H_DIM / 128, T_TOK / 128, E_NUM); // 16 x 16 x 8
    moe_gemm<I_DIM/32, I_DIM, H_DIM, H_DIM, false><<<grid2, 256, SMEM_BYTES>>>(nullptr, w2);

    combine_kernel<<<(T_TOK * (H_DIM / 4) + 255) / 256, 256>>>(out);
}

// round 11
// speedup vs baseline: 2.1569x; 1.2342x over previous
#include <cuda_runtime.h>
#include <cuda_bf16.h>
#include <math.h>
#include <stdint.h>

// ---------------- problem constants ----------------
#define T_TOK 2048
#define H_DIM 2048
#define I_DIM 1408
#define N1    (2*I_DIM)     // 2816
#define E_NUM 8
#define NPAIR (2*T_TOK)     // 4096

// ---------------- device scratch ----------------
__device__ int   g_cnt[E_NUM];
__device__ int   g_off[E_NUM];
__device__ int   g_cur[E_NUM];
__device__ int   g_tok_e[T_TOK][2];
__device__ float g_tok_w[T_TOK][2];
__device__ int   g_tok_row[T_TOK][2];
__device__ int   g_row_tok[NPAIR];
__device__ float g_gu[NPAIR][N1];      // gate_up (fp32)
__device__ float g_eo[NPAIR][H_DIM];   // expert_out (unweighted fp32)

// pre-split bf16 hi/lo operands
__device__ __nv_bfloat16 g_x_hi[T_TOK][H_DIM];
__device__ __nv_bfloat16 g_x_lo[T_TOK][H_DIM];
__device__ __nv_bfloat16 g_w1_hi[E_NUM][N1][H_DIM];
__device__ __nv_bfloat16 g_w1_lo[E_NUM][N1][H_DIM];
__device__ __nv_bfloat16 g_w2_hi[E_NUM][H_DIM][I_DIM];
__device__ __nv_bfloat16 g_w2_lo[E_NUM][H_DIM][I_DIM];
__device__ __nv_bfloat16 g_act_hi[NPAIR][I_DIM];
__device__ __nv_bfloat16 g_act_lo[NPAIR][I_DIM];

// ---------------- helpers ----------------
__device__ __forceinline__ uint32_t smem_u32(const void* p) {
    uint32_t a;
    asm("{ .reg .u64 t; cvta.to.shared.u64 t, %1; cvt.u32.u64 %0, t; }" : "=r"(a) : "l"(p));
    return a;
}
#define CP16(dst, src, nbytes) \
    asm volatile("cp.async.ca.shared.global [%0], [%1], 16, %2;" \
                 :: "r"(dst), "l"(src), "r"(nbytes))
#define CP_COMMIT() asm volatile("cp.async.commit_group;" ::: "memory")
#define CP_WAIT(n)  asm volatile("cp.async.wait_group %0;" :: "n"(n) : "memory")

#define LDSM4(r0, r1, r2, r3, addr) \
    asm volatile("ldmatrix.sync.aligned.m8n8.x4.shared.b16 {%0,%1,%2,%3}, [%4];" \
                 : "=r"(r0), "=r"(r1), "=r"(r2), "=r"(r3) : "r"(addr))

__device__ __forceinline__ void mma_bf16(float& c0, float& c1, float& c2, float& c3,
                                         uint32_t a0, uint32_t a1, uint32_t a2, uint32_t a3,
                                         uint32_t b0, uint32_t b1) {
    asm volatile(
        "mma.sync.aligned.m16n8k16.row.col.f32.bf16.bf16.f32 "
        "{%0,%1,%2,%3}, {%4,%5,%6,%7}, {%8,%9}, {%0,%1,%2,%3};"
        : "+f"(c0), "+f"(c1), "+f"(c2), "+f"(c3)
        : "r"(a0), "r"(a1), "r"(a2), "r"(a3), "r"(b0), "r"(b1));
}

// split fp32 pair (x, y) -> packed bf16x2 hi (low half = x) + bf16x2 lo residual
__device__ __forceinline__ void split2(float x, float y, uint32_t& hi, uint32_t& lo) {
    uint32_t h;
    asm("cvt.rn.bf16x2.f32 %0, %1, %2;" : "=r"(h) : "f"(y), "f"(x));
    float hx = __uint_as_float(h << 16);
    float hy = __uint_as_float(h & 0xFFFF0000u);
    float lx = x - hx, ly = y - hy;
    asm("cvt.rn.bf16x2.f32 %0, %1, %2;" : "=r"(lo) : "f"(ly), "f"(lx));
    hi = h;
}

// smem: 4 tiles per buffer (Ahi, Alo, Bhi, Blo), 128 rows x 32 bf16, row stride 40 bf16 (80B)
#define SRB        80            // row stride bytes
#define TILE_B     (128 * SRB)   // 10240
#define OFF_ALO    TILE_B
#define OFF_BHI    (2 * TILE_B)
#define OFF_BLO    (3 * TILE_B)
#define BUF_B      (4 * TILE_B)  // 40960
#define SMEM_BYTES (2 * BUF_B)   // 81920

// ---------------- init / gating / scatter ----------------
__global__ void init_kernel() {
    int i = threadIdx.x;
    if (i < E_NUM) { g_cnt[i] = 0; g_cur[i] = 0; }
}

__global__ void gate_kernel(const float* __restrict__ x, const float* __restrict__ gw) {
    __shared__ float sx[H_DIM];
    __shared__ float logits[E_NUM];
    int t = blockIdx.x;
    const float* xr = x + (size_t)t * H_DIM;
    for (int i = threadIdx.x; i < H_DIM; i += blockDim.x) sx[i] = xr[i];
    __syncthreads();
    int w = threadIdx.x >> 5, lane = threadIdx.x & 31;
    const float* gr = gw + (size_t)w * H_DIM;
    float s = 0.f;
    for (int i = lane; i < H_DIM; i += 32) s += sx[i] * gr[i];
    #pragma unroll
    for (int o = 16; o; o >>= 1) s += __shfl_xor_sync(0xffffffffu, s, o);
    if (lane == 0) logits[w] = s;
    __syncthreads();
    if (threadIdx.x == 0) {
        int i0 = 0;
        #pragma unroll
        for (int e = 1; e < E_NUM; e++) if (logits[e] > logits[i0]) i0 = e;
        int i1 = (i0 == 0) ? 1 : 0;
        #pragma unroll
        for (int e = 0; e < E_NUM; e++) {
            if (e == i0 || e == i1) continue;
            if (logits[e] > logits[i1]) i1 = e;
        }
        float ex = expf(logits[i1] - logits[i0]);
        float w0 = 1.f / (1.f + ex);
        float w1 = ex / (1.f + ex);
        g_tok_e[t][0] = i0; g_tok_e[t][1] = i1;
        g_tok_w[t][0] = w0; g_tok_w[t][1] = w1;
        atomicAdd(&g_cnt[i0], 1); atomicAdd(&g_cnt[i1], 1);
    }
}

__global__ void offs_kernel() {
    if (threadIdx.x == 0) {
        int o = 0;
        #pragma unroll
        for (int e = 0; e < E_NUM; e++) { g_off[e] = o; o += g_cnt[e]; }
    }
}

__global__ void scatter_kernel() {
    int t = blockIdx.x * blockDim.x + threadIdx.x;
    if (t >= T_TOK) return;
    #pragma unroll
    for (int k = 0; k < 2; k++) {
        int e = g_tok_e[t][k];
        int p = atomicAdd(&g_cur[e], 1);
        int r = g_off[e] + p;
        g_row_tok[r] = t;
        g_tok_row[t][k] = r;
    }
}

// ---------------- pre-split fp32 -> bf16 hi/lo ----------------
// DST: 0 = x, 1 = w1, 2 = w2 (destinations resolved in DEVICE code)
template<int DST>
__global__ void split_kernel(const float* __restrict__ in, int n4) {
    int idx = blockIdx.x * blockDim.x + threadIdx.x;
    if (idx >= n4) return;
    __nv_bfloat16* hi;
    __nv_bfloat16* lo;
    if (DST == 0)      { hi = &g_x_hi[0][0];     lo = &g_x_lo[0][0]; }
    else if (DST == 1) { hi = &g_w1_hi[0][0][0]; lo = &g_w1_lo[0][0][0]; }
    else               { hi = &g_w2_hi[0][0][0]; lo = &g_w2_lo[0][0][0]; }
    float4 v = ((const float4*)in)[idx];
    uint32_t h01, l01, h23, l23;
    split2(v.x, v.y, h01, l01);
    split2(v.z, v.w, h23, l23);
    ((uint2*)hi)[idx] = make_uint2(h01, h23);
    ((uint2*)lo)[idx] = make_uint2(l01, l23);
}

// ---------------- bf16x3 mma.sync grouped GEMM (pre-split operands) ----------
// C[row, n] = sum_k A[row, k] * W_e[n, k]
// 128x128x32 tiles; 8 warps (2m x 4n), warp tile 64x32, m16n8k16 bf16 HMMA via
// ldmatrix; 3 products per fragment pair: hh + h*lo + lo*h.
// All operand/output arrays are device globals resolved in device code.
template<int NK, int KSTRIDE, int NROWS, int OUTSTRIDE, bool GATHER>
__global__ __launch_bounds__(256, 1)
void moe_gemm() {
    extern __shared__ char smc[];
    const int e    = blockIdx.z;
    const int cnt  = g_cnt[e];
    const int base = g_off[e];
    const int m0   = blockIdx.y * 128;
    if (m0 >= cnt) return;
    const int n0 = blockIdx.x * 128;

    // device-side pointer resolution (host cannot take &__device__ symbols!)
    const __nv_bfloat16* aHi;
    const __nv_bfloat16* aLo;
    const __nv_bfloat16* wHi;
    const __nv_bfloat16* wLo;
    float* Out;
    if (GATHER) {
        aHi = &g_x_hi[0][0];      aLo = &g_x_lo[0][0];
        wHi = &g_w1_hi[0][0][0];  wLo = &g_w1_lo[0][0][0];
        Out = &g_gu[0][0];
    } else {
        aHi = &g_act_hi[0][0];    aLo = &g_act_lo[0][0];
        wHi = &g_w2_hi[0][0][0];  wLo = &g_w2_lo[0][0][0];
        Out = &g_eo[0][0];
    }

    const uint32_t smb = smem_u32(smc);
    const int tid  = threadIdx.x;
    const int lane = tid & 31;
    const int wid  = tid >> 5;
    const int wm   = wid >> 2;            // m offset wm*64
    const int wn   = wid & 3;             // n offset wn*32

    // staging: thread -> one row, half of its 4x16B chunks, all 4 tiles
    const int srow = tid >> 1;            // 0..127
    const int half = tid & 1;             // chunks {0,1} or {2,3}
    const bool a_ok = (m0 + srow) < cnt;
    int arow_idx;
    if (GATHER) arow_idx = a_ok ? g_row_tok[base + m0 + srow] : 0;
    else        arow_idx = a_ok ? (base + m0 + srow) : 0;
    const __nv_bfloat16* aHiRow = aHi + (size_t)arow_idx * KSTRIDE;
    const __nv_bfloat16* aLoRow = aLo + (size_t)arow_idx * KSTRIDE;
    const __nv_bfloat16* bHiRow = wHi + (size_t)e * NROWS * KSTRIDE + (size_t)(n0 + srow) * KSTRIDE;
    const __nv_bfloat16* bLoRow = wLo + (size_t)e * NROWS * KSTRIDE + (size_t)(n0 + srow) * KSTRIDE;
    const int a_n = a_ok ? 16 : 0;

    auto stage = [&](int kt, int b) {
        uint32_t s0 = smb + (uint32_t)(b * BUF_B);
        #pragma unroll
        for (int j = 0; j < 2; j++) {
            int c = half * 2 + j;                      // 16B chunk 0..3
            uint32_t doff = (uint32_t)(srow * SRB + c * 16);
            int goff = kt * 32 + c * 8;                // bf16 elements
            CP16(s0 + doff,           aHiRow + goff, a_n);
            CP16(s0 + OFF_ALO + doff, aLoRow + goff, a_n);
            CP16(s0 + OFF_BHI + doff, bHiRow + goff, 16);
            CP16(s0 + OFF_BLO + doff, bLoRow + goff, 16);
        }
        CP_COMMIT();
    };

    stage(0, 0);
    stage(1, 1);

    float acc[4][4][4];
    #pragma unroll
    for (int i = 0; i < 4; i++)
        #pragma unroll
        for (int j = 0; j < 4; j++)
            #pragma unroll
            for (int q = 0; q < 4; q++) acc[i][j][q] = 0.f;

    // ldmatrix per-lane base offsets
    const int quad = lane >> 3, lr = lane & 7;
    const uint32_t a_base = (uint32_t)((wm * 64 + (quad & 1) * 8 + lr) * SRB + (quad >> 1) * 16);
    const uint32_t b_base = (uint32_t)((wn * 32 + (quad >> 1) * 8 + lr) * SRB + (quad & 1) * 16);

    for (int kt = 0; kt < NK; kt++) {
        if (kt == NK - 1) CP_WAIT(0); else CP_WAIT(1);
        __syncthreads();
        const uint32_t bufa = smb + (uint32_t)((kt & 1) * BUF_B);
        #pragma unroll
        for (int ks = 0; ks < 2; ks++) {
            const uint32_t ko = (uint32_t)(ks * 32);   // k16 step = 32B
            uint32_t ah[4][4], al[4][4];
            #pragma unroll
            for (int mf = 0; mf < 4; mf++) {
                uint32_t ad = bufa + a_base + (uint32_t)(mf * 16 * SRB) + ko;
                LDSM4(ah[mf][0], ah[mf][1], ah[mf][2], ah[mf][3], ad);
                LDSM4(al[mf][0], al[mf][1], al[mf][2], al[mf][3], ad + OFF_ALO);
            }
            uint32_t bh[4][2], bl[4][2];
            #pragma unroll
            for (int p = 0; p < 2; p++) {
                uint32_t bd = bufa + OFF_BHI + b_base + (uint32_t)(p * 16 * SRB) + ko;
                uint32_t t0, t1, t2, t3;
                LDSM4(t0, t1, t2, t3, bd);
                bh[2*p][0] = t0; bh[2*p][1] = t1; bh[2*p+1][0] = t2; bh[2*p+1][1] = t3;
                LDSM4(t0, t1, t2, t3, bd + TILE_B);  // Blo = Bhi + TILE_B
                bl[2*p][0] = t0; bl[2*p][1] = t1; bl[2*p+1][0] = t2; bl[2*p+1][1] = t3;
            }
            #pragma unroll
            for (int mf = 0; mf < 4; mf++)
                #pragma unroll
                for (int nf = 0; nf < 4; nf++) {
                    mma_bf16(acc[mf][nf][0], acc[mf][nf][1], acc[mf][nf][2], acc[mf][nf][3],
                             ah[mf][0], ah[mf][1], ah[mf][2], ah[mf][3],
                             bh[nf][0], bh[nf][1]);
                    mma_bf16(acc[mf][nf][0], acc[mf][nf][1], acc[mf][nf][2], acc[mf][nf][3],
                             ah[mf][0], ah[mf][1], ah[mf][2], ah[mf][3],
                             bl[nf][0], bl[nf][1]);
                    mma_bf16(acc[mf][nf][0], acc[mf][nf][1], acc[mf][nf][2], acc[mf][nf][3],
                             al[mf][0], al[mf][1], al[mf][2], al[mf][3],
                             bh[nf][0], bh[nf][1]);
                }
        }
        __syncthreads();
        if (kt + 2 < NK) stage(kt + 2, kt & 1);
    }

    const int qrow = lane >> 2;
    const int qk   = lane & 3;
    #pragma unroll
    for (int mf = 0; mf < 4; mf++) {
        int ml = wm * 64 + mf * 16 + qrow;
        int m1 = m0 + ml;
        int m2 = m1 + 8;
        #pragma unroll
        for (int nf = 0; nf < 4; nf++) {
            int col = n0 + wn * 32 + nf * 8 + qk * 2;
            if (m1 < cnt) {
                float2 v = make_float2(acc[mf][nf][0], acc[mf][nf][1]);
                *(float2*)(Out + (size_t)(base + m1) * OUTSTRIDE + col) = v;
            }
            if (m2 < cnt) {
                float2 v = make_float2(acc[mf][nf][2], acc[mf][nf][3]);
                *(float2*)(Out + (size_t)(base + m2) * OUTSTRIDE + col) = v;
            }
        }
    }
}

// ---------------- activation: act = silu(g) * u, split to bf16 hi/lo --------
__global__ void act_kernel() {
    int idx = blockIdx.x * blockDim.x + threadIdx.x;
    const int total = NPAIR * (I_DIM / 4);
    if (idx >= total) return;
    int r  = idx / (I_DIM / 4);
    int c4 = (idx % (I_DIM / 4)) * 4;
    float4 g = *(const float4*)&g_gu[r][c4];
    float4 u = *(const float4*)&g_gu[r][I_DIM + c4];
    float4 o;
    o.x = g.x / (1.f + expf(-g.x)) * u.x;
    o.y = g.y / (1.f + expf(-g.y)) * u.y;
    o.z = g.z / (1.f + expf(-g.z)) * u.z;
    o.w = g.w / (1.f + expf(-g.w)) * u.w;
    uint32_t h01, l01, h23, l23;
    split2(o.x, o.y, h01, l01);
    split2(o.z, o.w, h23, l23);
    *(uint2*)&g_act_hi[r][c4] = make_uint2(h01, h23);
    *(uint2*)&g_act_lo[r][c4] = make_uint2(l01, l23);
}

// ---------------- combine: out[t] = w0*eo[r0] + w1*eo[r1] ----------------
__global__ void combine_kernel(float* __restrict__ out) {
    int idx = blockIdx.x * blockDim.x + threadIdx.x;
    const int per_tok = H_DIM / 4;
    if (idx >= T_TOK * per_tok) return;
    int t  = idx / per_tok;
    int c4 = (idx % per_tok) * 4;
    int r0 = g_tok_row[t][0], r1 = g_tok_row[t][1];
    float w0 = g_tok_w[t][0], w1 = g_tok_w[t][1];
    float4 a = *(const float4*)&g_eo[r0][c4];
    float4 b = *(const float4*)&g_eo[r1][c4];
    float4 o;
    o.x = w0 * a.x + w1 * b.x;
    o.y = w0 * a.y + w1 * b.y;
    o.z = w0 * a.z + w1 * b.z;
    o.w = w0 * a.w + w1 * b.w;
    *(float4*)(out + (size_t)t * H_DIM + c4) = o;
}

// ---------------- launch ----------------
extern "C" void kernel_launch(void* const* d_in, const int* in_sizes, int n_in,
                              void* d_out, int out_size) {
    const float* x  = (const float*)d_in[0];
    const float* gw = (const float*)d_in[1];
    const float* w1 = (const float*)d_in[2];
    const float* w2 = (const float*)d_in[3];
    float* out = (float*)d_out;

    cudaFuncSetAttribute(moe_gemm<H_DIM/32, H_DIM, N1, N1, true>,
                         cudaFuncAttributeMaxDynamicSharedMemorySize, SMEM_BYTES);
    cudaFuncSetAttribute(moe_gemm<I_DIM/32, I_DIM, H_DIM, H_DIM, false>,
                         cudaFuncAttributeMaxDynamicSharedMemorySize, SMEM_BYTES);

    init_kernel<<<1, 32>>>();
    gate_kernel<<<T_TOK, 256>>>(x, gw);
    offs_kernel<<<1, 32>>>();
    scatter_kernel<<<(T_TOK + 255) / 256, 256>>>();

    // pre-split operands to bf16 hi/lo (destinations resolved device-side)
    {
        int n4 = T_TOK * H_DIM / 4;
        split_kernel<0><<<(n4 + 255) / 256, 256>>>(x, n4);
        n4 = E_NUM * N1 * H_DIM / 4;
        split_kernel<1><<<(n4 + 255) / 256, 256>>>(w1, n4);
        n4 = E_NUM * H_DIM * I_DIM / 4;
        split_kernel<2><<<(n4 + 255) / 256, 256>>>(w2, n4);
    }

    dim3 grid1(N1 / 128, T_TOK / 128, E_NUM);    // 22 x 16 x 8
    moe_gemm<H_DIM/32, H_DIM, N1, N1, true><<<grid1, 256, SMEM_BYTES>>>();

    int actth = NPAIR * (I_DIM / 4);
    act_kernel<<<(actth + 255) / 256, 256>>>();

    dim3 grid2(H_DIM / 128, T_TOK / 128, E_NUM); // 16 x 16 x 8
    moe_gemm<I_DIM/32, I_DIM, H_DIM, H_DIM, false><<<grid2, 256, SMEM_BYTES>>>();

    combine_kernel<<<(T_TOK * (H_DIM / 4) + 255) / 256, 256>>>(out);
}